// round 5
// baseline (speedup 1.0000x reference)
#include <cuda_runtime.h>

#define NEGF  (-1e30f)
#define LOG2E (1.4426950408889634f)
#define LN2   (0.6931471805599453f)
#define MAXB  4096
#define SP    264                    // padded row stride of P (floats)
#define MAXBT (64 * 1024)

__device__ float g_loss[MAXB];
__device__ float g_P[(size_t)MAXBT * SP];   // P[b][t][j] = log2e * lp[b][t][ext_label(j)]

__device__ __forceinline__ float ex2f_(float x){ float y; asm("ex2.approx.f32 %0,%1;":"=f"(y):"f"(x)); return y; }
__device__ __forceinline__ float lg2f_(float x){ float y; asm("lg2.approx.f32 %0,%1;":"=f"(y):"f"(x)); return y; }

__device__ __forceinline__ float lae2(float x, float y) {
    float m = fmaxf(x, y);
    float d = -fabsf(x - y);
    return m + lg2f_(1.0f + ex2f_(d));
}
__device__ __forceinline__ float lae3(float x, float y, float z) {
    float m = fmaxf(fmaxf(x, y), z);
    float t = ex2f_(x - m) + ex2f_(y - m) + ex2f_(z - m);
    return m + lg2f_(t);
}

// -------- pre-pass: P[b][t][0] = blank lp, P[b][t][1+j] = lp of label tg[j], scaled by log2e
#define TCHUNK 4
__global__ void ctc_gather_kernel(
    const float* __restrict__ lp,      // [B, T, V]
    const int*   __restrict__ in_len,
    const int*   __restrict__ targets, // [B, S]
    const int*   __restrict__ tgt_len,
    int T, int V, int S)
{
    const int nb = T / TCHUNK;         // chunks per batch row
    const int b  = blockIdx.x / nb;
    const int t0 = (blockIdx.x % nb) * TCHUNK;
    const int j  = threadIdx.x;

    const int L   = tgt_len[b];
    int Tin = in_len[b]; if (Tin > T) Tin = T;

    if (j > S || j > L) return;        // only rows the serial kernel reads
    const int lab = (j == 0) ? 0 : targets[b * S + j - 1];

    const float* src = lp  + ((size_t)b * T + t0) * V + lab;
    float*       dst = g_P + ((size_t)b * T + t0) * SP + j;
    #pragma unroll
    for (int k = 0; k < TCHUNK; ++k) {
        int t = t0 + k;
        if (t < Tin) dst[(size_t)k * SP] = src[(size_t)k * V] * LOG2E;
    }
}

// -------- serial forward: one thread owns pair (2j blank, 2j+1 label)
__global__ void __launch_bounds__(288) ctc_fwd_kernel(
    const int* __restrict__ in_len,
    const int* __restrict__ targets,
    const int* __restrict__ tgt_len,
    int T, int S)
{
    extern __shared__ float smem[];
    const int BUF = S + 2;             // slot 0 = left pad (NEG forever)
    float* buf0 = smem;
    float* buf1 = smem + BUF;

    const int b = blockIdx.x;
    const int j = threadIdx.x;

    const int L = tgt_len[b];
    int Tin = in_len[b];
    if (Tin > T) Tin = T;
    if (Tin < 1) Tin = 1;

    const float* Pb = g_P + (size_t)b * T * SP;
    const int*   tg = targets + (size_t)b * S;

    const bool act  = (j <= L) && (j <= S);
    const bool act1 = (j <  L);
    bool sk = false;
    if (act1 && j >= 1) sk = (tg[j] != tg[j - 1]);

    for (int i = j; i < 2 * BUF; i += blockDim.x) smem[i] = NEGF;

    // t = 0 (already log2-scaled in P)
    float a0 = NEGF, a1 = NEGF;
    if (j == 0) {
        a0 = Pb[0];
        if (L > 0) a1 = Pb[1];
    }
    __syncthreads();
    if (act) buf0[1 + j] = a1;

    // 8-deep register prefetch rings (coalesced reads of P rows)
    float ring_b[8], ring_l[8];
    #pragma unroll
    for (int k = 0; k < 8; ++k) {
        int t = 1 + k;
        if (act && t < Tin) {
            ring_b[k] = Pb[(size_t)t * SP];
            ring_l[k] = Pb[(size_t)t * SP + 1 + j];   // j==L reads padding: discarded below
        } else { ring_b[k] = 0.0f; ring_l[k] = 0.0f; }
    }
    __syncthreads();

    float* bo = buf0;
    float* bn = buf1;
    for (int tb = 1; tb < Tin; tb += 8) {
        #pragma unroll
        for (int k = 0; k < 8; ++k) {
            const int t = tb + k;
            if (t < Tin) {                 // uniform per block
                if (act) {
                    const float bl = ring_b[k];
                    const float lv = ring_l[k];
                    const int tn = t + 8;
                    if (tn < Tin) {
                        ring_b[k] = Pb[(size_t)tn * SP];
                        ring_l[k] = Pb[(size_t)tn * SP + 1 + j];
                    }
                    const float o = bo[j];            // left neighbor's odd alpha
                    float n0 = lae2(a0, o) + bl;      // blank at 2j
                    float zz = sk ? o : NEGF;
                    float n1 = lae3(a1, a0, zz) + lv; // label at 2j+1 (garbage if !act1, discarded)
                    a0 = n0;
                    a1 = act1 ? n1 : NEGF;
                    bn[1 + j] = a1;
                }
                float* tmp = bo; bo = bn; bn = tmp;
                __syncthreads();
            }
        }
    }

    if (act) bn[1 + j] = a0;               // publish even alphas
    __syncthreads();

    if (j == 0) {
        float x = bn[1 + L];                       // alpha[2L]   (blank)
        float y = (L > 0) ? bo[L] : NEGF;          // alpha[2L-1]
        float ll2 = lae2(x, y);
        float loss = -ll2 * LN2;
        if (!(loss <= 1e29f)) loss = 0.0f;         // zero_infinity (+ nan guard)
        int Lm = (L > 0) ? L : 1;
        g_loss[b] = loss / (float)Lm;
    }
}

__global__ void ctc_reduce_kernel(float* __restrict__ out, int B) {
    int lane = threadIdx.x;
    float s = 0.0f;
    for (int i = lane; i < B; i += 32) s += g_loss[i];
    #pragma unroll
    for (int off = 16; off; off >>= 1)
        s += __shfl_xor_sync(0xffffffffu, s, off);
    if (lane == 0) out[0] = s / (float)B;
}

extern "C" void kernel_launch(void* const* d_in, const int* in_sizes, int n_in,
                              void* d_out, int out_size) {
    const float* log_probs = (const float*)d_in[0];
    const int*   in_len    = (const int*)d_in[1];
    const int*   targets   = (const int*)d_in[2];
    const int*   tgt_len   = (const int*)d_in[3];

    const int B = in_sizes[1];
    const int S = in_sizes[2] / B;
    const int V = 128;
    const int T = in_sizes[0] / (B * V);

    const int threads = ((S + 2 + 31) / 32) * 32;          // covers j = 0..S
    ctc_gather_kernel<<<B * (T / TCHUNK), threads>>>(log_probs, in_len, targets, tgt_len, T, V, S);

    const size_t smem = (size_t)(2 * (S + 2)) * sizeof(float);
    ctc_fwd_kernel<<<B, threads, smem>>>(in_len, targets, tgt_len, T, S);
    ctc_reduce_kernel<<<1, 32>>>((float*)d_out, B);
}

// round 6
// speedup vs baseline: 2.1313x; 2.1313x over previous
#include <cuda_runtime.h>

#define NEGF  (-1e30f)
#define LOG2E (1.4426950408889634f)
#define LN2   (0.6931471805599453f)
#define MAXB  4096
__device__ float g_loss[MAXB];

__device__ __forceinline__ float ex2f_(float x){ float y; asm("ex2.approx.f32 %0,%1;":"=f"(y):"f"(x)); return y; }
__device__ __forceinline__ float lg2f_(float x){ float y; asm("lg2.approx.f32 %0,%1;":"=f"(y):"f"(x)); return y; }

__device__ __forceinline__ float lae2(float x, float y) {
    float m = fmaxf(x, y);
    float d = -fabsf(x - y);
    return m + lg2f_(1.0f + ex2f_(d));
}
__device__ __forceinline__ float lae3(float x, float y, float z) {
    float m = fmaxf(fmaxf(x, y), z);
    float t = ex2f_(x - m) + ex2f_(y - m) + ex2f_(z - m);
    return m + lg2f_(t);
}

__device__ __forceinline__ void cp4(float* s, const float* g) {
    unsigned sa = (unsigned)__cvta_generic_to_shared(s);
    asm volatile("cp.async.ca.shared.global [%0], [%1], 4;" :: "r"(sa), "l"(g));
}
__device__ __forceinline__ void cp_commit() { asm volatile("cp.async.commit_group;"); }
__device__ __forceinline__ void cp_wait1()  { asm volatile("cp.async.wait_group 1;"); }

// One thread owns extended positions 2j (blank) and 2j+1 (label tg[j]).
// Global loads are staged via cp.async into double-buffered smem, one group
// per 8-step superstep -> no LDG on the per-step critical path.
__global__ void __launch_bounds__(288) ctc_fwd_kernel(
    const float* __restrict__ log_probs,   // [B, T, V]
    const int*   __restrict__ in_len,
    const int*   __restrict__ targets,     // [B, S]
    const int*   __restrict__ tgt_len,
    int T, int V, int S)
{
    extern __shared__ float smem[];
    const int BUF = S + 2;                 // slot 0 = left pad (NEG forever)
    float* buf0  = smem;
    float* buf1  = smem + BUF;
    float* stg_l = smem + 2 * BUF;         // [2][8][288]
    float* stg_b = stg_l + 16 * 288;       // [2][8]

    const int b = blockIdx.x;
    const int j = threadIdx.x;

    const int L = tgt_len[b];
    int Tin = in_len[b];
    if (Tin > T) Tin = T;
    if (Tin < 1) Tin = 1;

    const float* lp = log_probs + (size_t)b * T * V;
    const int*   tg = targets   + (size_t)b * S;

    const bool act  = (j <= L) && (j <= S);
    const bool act1 = (j <  L);
    int  lab = 0;
    bool sk  = false;
    if (act1) {
        lab = tg[j];
        if (j >= 1) sk = (lab != tg[j - 1]);
    }
    const bool blanker = (j >= 260 && j < 268);   // spare threads stage blank lp

    for (int i = j; i < 2 * BUF; i += blockDim.x) smem[i] = NEGF;

    // t = 0
    float a0 = NEGF, a1 = NEGF;
    if (j == 0) {
        a0 = lp[0] * LOG2E;
        if (L > 0) a1 = lp[lab] * LOG2E;
    }
    __syncthreads();                       // NEG init complete
    if (act) buf0[1 + j] = a1;             // published by first superstep barrier

    // prologue: stage group for t = 1..8 into buffer 0
    if (act) {
        #pragma unroll
        for (int k = 0; k < 8; ++k) {
            int t = 1 + k;
            if (t < Tin) cp4(&stg_l[k * 288 + j], lp + (size_t)t * V + lab);
        }
    }
    if (blanker) {
        int k = j - 260, t = 1 + k;
        if (t < Tin) cp4(&stg_b[k], lp + (size_t)t * V);
    }
    cp_commit();

    float* bo = buf0;
    float* bn = buf1;
    int cur = 0;
    for (int tb = 1; tb < Tin; tb += 8, cur ^= 1) {
        const int nxt = cur ^ 1;
        // fire-and-forget next superstep's stage
        if (act) {
            #pragma unroll
            for (int k = 0; k < 8; ++k) {
                int tn = tb + 8 + k;
                if (tn < Tin) cp4(&stg_l[(nxt * 8 + k) * 288 + j], lp + (size_t)tn * V + lab);
            }
        }
        if (blanker) {
            int k = j - 260, tn = tb + 8 + k;
            if (tn < Tin) cp4(&stg_b[nxt * 8 + k], lp + (size_t)tn * V);
        }
        cp_commit();
        cp_wait1();                        // group 'cur' fully landed
        __syncthreads();                   // publish stage + alpha buffers

        // bulk-copy staged values to registers (all short-latency LDS)
        float rb[8], rl[8];
        #pragma unroll
        for (int k = 0; k < 8; ++k) {
            rb[k] = stg_b[cur * 8 + k] * LOG2E;
            rl[k] = stg_l[(cur * 8 + k) * 288 + j] * LOG2E;
        }

        #pragma unroll
        for (int k = 0; k < 8; ++k) {
            const int t = tb + k;
            if (t < Tin) {                 // uniform per block
                if (act) {
                    const float o  = bo[j];              // left neighbor's odd alpha
                    const float zz = sk ? o : NEGF;
                    float n1 = lae3(a1, a0, zz) + rl[k]; // label at 2j+1
                    float n0 = lae2(a0, o) + rb[k];      // blank at 2j
                    a0 = n0;
                    a1 = act1 ? n1 : NEGF;
                    bn[1 + j] = a1;
                }
                float* tmp = bo; bo = bn; bn = tmp;
                __syncthreads();
            }
        }
    }

    if (act) bn[1 + j] = a0;               // publish even alphas
    __syncthreads();

    if (j == 0) {
        float x = bn[1 + L];                       // alpha[2L]   (blank)
        float y = (L > 0) ? bo[L] : NEGF;          // alpha[2L-1]
        float ll2 = lae2(x, y);
        float loss = -ll2 * LN2;
        if (!(loss <= 1e29f)) loss = 0.0f;         // zero_infinity (+ nan guard)
        int Lm = (L > 0) ? L : 1;
        g_loss[b] = loss / (float)Lm;
    }
}

__global__ void ctc_reduce_kernel(float* __restrict__ out, int B) {
    int lane = threadIdx.x;
    float s = 0.0f;
    for (int i = lane; i < B; i += 32) s += g_loss[i];
    #pragma unroll
    for (int off = 16; off; off >>= 1)
        s += __shfl_xor_sync(0xffffffffu, s, off);
    if (lane == 0) out[0] = s / (float)B;
}

extern "C" void kernel_launch(void* const* d_in, const int* in_sizes, int n_in,
                              void* d_out, int out_size) {
    const float* log_probs = (const float*)d_in[0];
    const int*   in_len    = (const int*)d_in[1];
    const int*   targets   = (const int*)d_in[2];
    const int*   tgt_len   = (const int*)d_in[3];

    const int B = in_sizes[1];
    const int S = in_sizes[2] / B;
    const int V = 128;
    const int T = in_sizes[0] / (B * V);

    const size_t smem = (size_t)(2 * (S + 2) + 16 * 288 + 16) * sizeof(float);
    ctc_fwd_kernel<<<B, 288, smem>>>(log_probs, in_len, targets, tgt_len, T, V, S);
    ctc_reduce_kernel<<<1, 32>>>((float*)d_out, B);
}

// round 7
// speedup vs baseline: 2.1879x; 1.0265x over previous
#include <cuda_runtime.h>

#define NEGF  (-1e30f)
#define LOG2E (1.4426950408889634f)
#define LN2   (0.6931471805599453f)
#define MAXB  4096
#define NW    11
#define NT    (NW * 32)          // 352 threads
#define PMAX  272                // max pair index + 1 (24*10+31 = 271)

__device__ float g_loss[MAXB];

__device__ __forceinline__ float ex2f_(float x){ float y; asm("ex2.approx.f32 %0,%1;":"=f"(y):"f"(x)); return y; }
__device__ __forceinline__ float lg2f_(float x){ float y; asm("lg2.approx.f32 %0,%1;":"=f"(y):"f"(x)); return y; }

__device__ __forceinline__ float lae2(float x, float y) {
    float m = fmaxf(x, y);
    float d = -fabsf(x - y);
    return m + lg2f_(1.0f + ex2f_(d));
}
__device__ __forceinline__ float lae3(float x, float y, float z) {
    float m = fmaxf(fmaxf(x, y), z);
    float t = ex2f_(x - m) + ex2f_(y - m) + ex2f_(z - m);
    return m + lg2f_(t);
}

__device__ __forceinline__ void cp4(float* s, const float* g) {
    unsigned sa = (unsigned)__cvta_generic_to_shared(s);
    asm volatile("cp.async.ca.shared.global [%0], [%1], 4;" :: "r"(sa), "l"(g));
}
__device__ __forceinline__ void cp_commit() { asm volatile("cp.async.commit_group;"); }
__device__ __forceinline__ void cp_wait1()  { asm volatile("cp.async.wait_group 1;"); }

// Pair p = positions (2p blank, 2p+1 label tg[p]).  p = 24*warp + lane.
// Warp 0: all lanes owned.  Warps >=1: lanes 0-7 = left halo (redundant),
// lanes 8-31 owned.  Halo degrades 1 lane/step -> 8 autonomous steps/warp.
__global__ void __launch_bounds__(NT) ctc_fwd_kernel(
    const float* __restrict__ log_probs,   // [B, T, V]
    const int*   __restrict__ in_len,
    const int*   __restrict__ targets,     // [B, S]
    const int*   __restrict__ tgt_len,
    int T, int V, int S)
{
    extern __shared__ float smem[];
    float* sa0   = smem;                   // [2][PMAX]
    float* sa1   = smem + 2 * PMAX;        // [2][PMAX]
    float* stg_b = smem + 4 * PMAX;        // [2][8]
    float* stg_l = stg_b + 16;             // [2][8][NT]

    const int b    = blockIdx.x;
    const int j    = threadIdx.x;
    const int warp = j >> 5;
    const int lane = j & 31;
    const int p    = 24 * warp + lane;
    const bool owned = (warp == 0) || (lane >= 8);

    const int L = tgt_len[b];
    int Tin = in_len[b];
    if (Tin > T) Tin = T;
    if (Tin < 1) Tin = 1;

    const float* lp = log_probs + (size_t)b * T * V;
    const int*   tg = targets   + (size_t)b * S;

    const bool act  = (p <= L);
    const bool act1 = (p <  L);
    const bool wact = (24 * warp) <= L;    // warp has at least one active lane
    int  lab = 0;
    bool sk  = false;
    if (act1) {
        lab = tg[p];
        if (p >= 1) sk = (lab != tg[p - 1]);
    }

    // t = 0 alphas (log2 space); publish to sa buffer 0 (first superstep's cur)
    float a0 = NEGF, a1 = NEGF;
    if (p == 0) {
        a0 = lp[0] * LOG2E;
        if (L > 0) a1 = lp[lab] * LOG2E;
    }
    if (owned) { sa0[p] = a0; sa1[p] = a1; }

    // prologue: stage two groups (t=1..8 -> buf0, t=9..16 -> buf1)
    if (act) {
        #pragma unroll
        for (int k = 0; k < 8; ++k) { int t = 1 + k; if (t < Tin) cp4(&stg_l[k * NT + j], lp + (size_t)t * V + lab); }
    }
    if (j >= NT - 8) { int k = j - (NT - 8), t = 1 + k; if (t < Tin) cp4(&stg_b[k], lp + (size_t)t * V); }
    cp_commit();
    if (act) {
        #pragma unroll
        for (int k = 0; k < 8; ++k) { int t = 9 + k; if (t < Tin) cp4(&stg_l[(8 + k) * NT + j], lp + (size_t)t * V + lab); }
    }
    if (j >= NT - 8) { int k = j - (NT - 8), t = 9 + k; if (t < Tin) cp4(&stg_b[8 + k], lp + (size_t)t * V); }
    cp_commit();

    int cur = 0;
    for (int tb = 1; tb < Tin; tb += 8, cur ^= 1) {
        cp_wait1();                        // group 'cur' landed
        __syncthreads();                   // A: publish stage[cur] + sa[cur]

        if (!owned) { a0 = sa0[cur * PMAX + p]; a1 = sa1[cur * PMAX + p]; }  // halo refresh

        float rb[8], rl[8];
        #pragma unroll
        for (int k = 0; k < 8; ++k) rb[k] = stg_b[cur * 8 + k] * LOG2E;
        if (act) {
            #pragma unroll
            for (int k = 0; k < 8; ++k) rl[k] = stg_l[(cur * 8 + k) * NT + j] * LOG2E;
        }
        __syncthreads();                   // B: stage[cur] fully consumed

        // refill stage[cur] for t = tb+16 .. tb+23 (fire and forget)
        if (act) {
            #pragma unroll
            for (int k = 0; k < 8; ++k) { int tn = tb + 16 + k; if (tn < Tin) cp4(&stg_l[(cur * 8 + k) * NT + j], lp + (size_t)tn * V + lab); }
        }
        if (j >= NT - 8) { int k = j - (NT - 8), tn = tb + 16 + k; if (tn < Tin) cp4(&stg_b[cur * 8 + k], lp + (size_t)tn * V); }
        cp_commit();

        // ---- 8 steps: pure shfl + MUFU, no barriers ----
        if (wact) {
            #pragma unroll
            for (int k = 0; k < 8; ++k) {
                if (tb + k < Tin) {        // block-uniform
                    float o = __shfl_up_sync(0xffffffffu, a1, 1);
                    if (lane == 0) o = NEGF;
                    if (act) {
                        float zz = sk ? o : NEGF;
                        float n1 = lae3(a1, a0, zz) + rl[k];
                        float n0 = lae2(a0, o) + rb[k];
                        a0 = n0;
                        a1 = act1 ? n1 : NEGF;
                    }
                }
            }
        }

        // publish owned alphas for next superstep's halo
        const int nxt = cur ^ 1;
        if (owned) { sa0[nxt * PMAX + p] = a0; sa1[nxt * PMAX + p] = a1; }
    }

    // epilogue: gather alpha[2L], alpha[2L-1]
    __syncthreads();
    if (owned) { sa0[p] = a0; sa1[p] = a1; }
    __syncthreads();
    if (j == 0) {
        float x = sa0[L];                          // alpha[2L]   (blank)
        float y = (L > 0) ? sa1[L - 1] : NEGF;     // alpha[2L-1]
        float ll2 = lae2(x, y);
        float loss = -ll2 * LN2;
        if (!(loss <= 1e29f)) loss = 0.0f;         // zero_infinity (+ nan guard)
        int Lm = (L > 0) ? L : 1;
        g_loss[b] = loss / (float)Lm;
    }
}

__global__ void ctc_reduce_kernel(float* __restrict__ out, int B) {
    int lane = threadIdx.x;
    float s = 0.0f;
    for (int i = lane; i < B; i += 32) s += g_loss[i];
    #pragma unroll
    for (int off = 16; off; off >>= 1)
        s += __shfl_xor_sync(0xffffffffu, s, off);
    if (lane == 0) out[0] = s / (float)B;
}

extern "C" void kernel_launch(void* const* d_in, const int* in_sizes, int n_in,
                              void* d_out, int out_size) {
    const float* log_probs = (const float*)d_in[0];
    const int*   in_len    = (const int*)d_in[1];
    const int*   targets   = (const int*)d_in[2];
    const int*   tgt_len   = (const int*)d_in[3];

    const int B = in_sizes[1];
    const int S = in_sizes[2] / B;
    const int V = 128;
    const int T = in_sizes[0] / (B * V);

    const size_t smem = (size_t)(4 * PMAX + 16 + 16 * NT) * sizeof(float);
    ctc_fwd_kernel<<<B, NT, smem>>>(log_probs, in_len, targets, tgt_len, T, V, S);
    ctc_reduce_kernel<<<1, 32>>>((float*)d_out, B);
}

// round 8
// speedup vs baseline: 2.3563x; 1.0770x over previous
#include <cuda_runtime.h>

#define NEGF  (-1e30f)
#define LOG2E (1.4426950408889634f)
#define LN2   (0.6931471805599453f)
#define MAXB  4096
#define NW    11
#define NT    (NW * 32)          // 352 threads
#define PMAX  272                // covers pairs 0..271 (need <= 257)

__device__ float g_loss[MAXB];

__device__ __forceinline__ float ex2f_(float x){ float y; asm("ex2.approx.f32 %0,%1;":"=f"(y):"f"(x)); return y; }
__device__ __forceinline__ float lg2f_(float x){ float y; asm("lg2.approx.f32 %0,%1;":"=f"(y):"f"(x)); return y; }

__device__ __forceinline__ float lae2(float x, float y) {
    float m = fmaxf(x, y);
    float d = -fabsf(x - y);
    return m + lg2f_(1.0f + ex2f_(d));
}

__device__ __forceinline__ void cp4(float* s, const float* g) {
    unsigned sa = (unsigned)__cvta_generic_to_shared(s);
    asm volatile("cp.async.ca.shared.global [%0], [%1], 4;" :: "r"(sa), "l"(g));
}
__device__ __forceinline__ void cp_commit() { asm volatile("cp.async.commit_group;"); }
__device__ __forceinline__ void cp_wait1()  { asm volatile("cp.async.wait_group 1;"); }

// Pair p = positions (2p blank, 2p+1 label tg[p]).  p = 24*warp + lane.
// Warps >=1: lanes 0-7 left halo (redundant), lanes 8-31 owned.
// Inner 8 steps: branch-free, shfl + fused dual-lae (3 EX2 + 2 LG2).
__global__ void __launch_bounds__(NT) ctc_fwd_kernel(
    const float* __restrict__ log_probs,   // [B, T, V]
    const int*   __restrict__ in_len,
    const int*   __restrict__ targets,     // [B, S]
    const int*   __restrict__ tgt_len,
    int T, int V, int S)
{
    __shared__ float sa0[2 * PMAX];
    __shared__ float sa1[2 * PMAX];
    __shared__ float stgl[16 * NT];        // [2][8][NT]  thread-private slots
    __shared__ float stgb[16 * NW];        // [2][8][NW]  warp-private blank slots

    const int b    = blockIdx.x;
    const int j    = threadIdx.x;
    const int warp = j >> 5;
    const int lane = j & 31;
    const int p    = 24 * warp + lane;
    const bool owned = (warp == 0) || (lane >= 8);

    int L = tgt_len[b]; if (L > S) L = S;
    int Tin = in_len[b];
    if (Tin > T) Tin = T;
    if (Tin < 1) Tin = 1;

    const float* lp = log_probs + (size_t)b * T * V;
    const int*   tg = targets   + (size_t)b * S;

    const bool act  = (p <= L);
    const bool act1 = (p <  L);
    const bool wact = (24 * warp) <= L;
    int   lab = 0;
    float skf = 0.0f;                      // 1.0 if s-2 skip allowed
    if (act1) {
        lab = tg[p];
        skf = (p >= 1 && lab != tg[p - 1]) ? 1.0f : 0.0f;
    }

    // t = 0 alphas (log2 space); publish to buffer 0
    float a0 = NEGF, a1 = NEGF;
    if (p == 0) {
        a0 = lp[0] * LOG2E;
        if (L > 0) a1 = lp[lab] * LOG2E;
    }
    if (owned) { sa0[p] = a0; sa1[p] = a1; }

    // prologue: stage t=1..8 -> buf0, t=9..16 -> buf1
    if (act) {
        #pragma unroll
        for (int k = 0; k < 8; ++k) { int t = 1 + k; if (t < Tin) cp4(&stgl[k * NT + j], lp + (size_t)t * V + lab); }
    }
    if (wact && lane >= 24) { int k = lane - 24, t = 1 + k; if (t < Tin) cp4(&stgb[k * NW + warp], lp + (size_t)t * V); }
    cp_commit();
    if (act) {
        #pragma unroll
        for (int k = 0; k < 8; ++k) { int t = 9 + k; if (t < Tin) cp4(&stgl[(8 + k) * NT + j], lp + (size_t)t * V + lab); }
    }
    if (wact && lane >= 24) { int k = lane - 24, t = 9 + k; if (t < Tin) cp4(&stgb[(8 + k) * NW + warp], lp + (size_t)t * V); }
    cp_commit();

    int cur = 0;
    for (int tb = 1; tb < Tin; tb += 8, cur ^= 1) {
        cp_wait1();                        // own group 'cur' landed
        __syncthreads();                   // cross-thread visibility: stage[cur] + sa[cur]

        if (wact) {
            if (!owned) { a0 = sa0[cur * PMAX + p]; a1 = sa1[cur * PMAX + p]; }  // halo refresh

            float rb[8], rl[8];
            #pragma unroll
            for (int k = 0; k < 8; ++k) {
                rb[k] = stgb[(cur * 8 + k) * NW + warp] * LOG2E;   // warp broadcast
                rl[k] = stgl[(cur * 8 + k) * NT + j]   * LOG2E;    // own slot
            }

            // refill stage[cur] for t = tb+16..tb+23 (slots are self-owned: no WAR)
            if (act) {
                #pragma unroll
                for (int k = 0; k < 8; ++k) { int tn = tb + 16 + k; if (tn < Tin) cp4(&stgl[(cur * 8 + k) * NT + j], lp + (size_t)tn * V + lab); }
            }
            if (lane >= 24) { int k = lane - 24, tn = tb + 16 + k; if (tn < Tin) cp4(&stgb[(cur * 8 + k) * NW + warp], lp + (size_t)tn * V); }

            int rem = Tin - tb; if (rem > 8) rem = 8;
            const int rem0 = act  ? rem : 0;
            const int rem1 = act1 ? rem : 0;

            // ---- 8 branch-free steps ----
            #pragma unroll
            for (int k = 0; k < 8; ++k) {
                float o = __shfl_up_sync(0xffffffffu, a1, 1);
                o = (lane == 0) ? NEGF : o;
                float m  = fmaxf(fmaxf(a0, a1), o);
                float e1 = ex2f_(a1 - m);
                float e0 = ex2f_(a0 - m);
                float eo = ex2f_(o  - m);
                float s1 = fmaf(skf, eo, e1 + e0 + 1e-30f);
                float s0 = e0 + eo + 1e-30f;
                float n1 = m + lg2f_(s1) + rl[k];
                float n0 = m + lg2f_(s0) + rb[k];
                a0 = (k < rem0) ? n0 : a0;     // freeze: tail / inactive
                a1 = (k < rem1) ? n1 : a1;     // keeps NEGF for p >= L
            }
        }
        cp_commit();                       // uniform; pairs with refills above

        const int nxt = cur ^ 1;
        if (owned) { sa0[nxt * PMAX + p] = a0; sa1[nxt * PMAX + p] = a1; }  // for next halo
    }

    // epilogue: gather alpha[2L], alpha[2L-1]
    __syncthreads();
    if (owned) { sa0[p] = a0; sa1[p] = a1; }
    __syncthreads();
    if (j == 0) {
        float x = sa0[L];                          // alpha[2L]   (blank)
        float y = (L > 0) ? sa1[L - 1] : NEGF;     // alpha[2L-1]
        float ll2 = lae2(x, y);
        float loss = -ll2 * LN2;
        if (!(loss <= 1e29f)) loss = 0.0f;         // zero_infinity (+ nan guard)
        int Lm = (L > 0) ? L : 1;
        g_loss[b] = loss / (float)Lm;
    }
}

__global__ void ctc_reduce_kernel(float* __restrict__ out, int B) {
    int lane = threadIdx.x;
    float s = 0.0f;
    for (int i = lane; i < B; i += 32) s += g_loss[i];
    #pragma unroll
    for (int off = 16; off; off >>= 1)
        s += __shfl_xor_sync(0xffffffffu, s, off);
    if (lane == 0) out[0] = s / (float)B;
}

extern "C" void kernel_launch(void* const* d_in, const int* in_sizes, int n_in,
                              void* d_out, int out_size) {
    const float* log_probs = (const float*)d_in[0];
    const int*   in_len    = (const int*)d_in[1];
    const int*   targets   = (const int*)d_in[2];
    const int*   tgt_len   = (const int*)d_in[3];

    const int B = in_sizes[1];
    const int S = in_sizes[2] / B;
    const int V = 128;
    const int T = in_sizes[0] / (B * V);

    ctc_fwd_kernel<<<B, NT>>>(log_probs, in_len, targets, tgt_len, T, V, S);
    ctc_reduce_kernel<<<1, 32>>>((float*)d_out, B);
}

// round 11
// speedup vs baseline: 2.9197x; 1.2391x over previous
#include <cuda_runtime.h>

#define NEGF  (-1e30f)
#define LOG2E (1.4426950408889634f)
#define LN2   (0.6931471805599453f)
#define MAXB  4096
#define NW    11
#define NT    (NW * 32)          // 352 threads
#define PMAX  272
#define EBIAS 100                // per-superstep renorm target: warp max = 2^EBIAS

__device__ float g_loss[MAXB];

__device__ __forceinline__ float ex2f_(float x){ float y; asm("ex2.approx.f32 %0,%1;":"=f"(y):"f"(x)); return y; }
__device__ __forceinline__ float lg2f_(float x){ float y; asm("lg2.approx.f32 %0,%1;":"=f"(y):"f"(x)); return y; }

__device__ __forceinline__ float lae2(float x, float y) {
    float m = fmaxf(x, y);
    float d = -fabsf(x - y);
    return m + lg2f_(1.0f + ex2f_(d));
}

// v * 2^d, exact power-of-2 factors, d clamped to [-252, 252]
__device__ __forceinline__ float ldx2(float v, int d) {
    d = d > 252 ? 252 : (d < -252 ? -252 : d);
    int d1 = d >> 1, d2 = d - d1;
    v *= __int_as_float((127 + d1) << 23);
    v *= __int_as_float((127 + d2) << 23);
    return v;
}

__device__ __forceinline__ void cp4(float* s, const float* g) {
    unsigned sa = (unsigned)__cvta_generic_to_shared(s);
    asm volatile("cp.async.ca.shared.global [%0], [%1], 4;" :: "r"(sa), "l"(g));
}
__device__ __forceinline__ void cp_commit() { asm volatile("cp.async.commit_group;"); }
__device__ __forceinline__ void cp_wait1()  { asm volatile("cp.async.wait_group 1;"); }

// Pair p = (2p blank, 2p+1 label tg[p]).  p = 24*warp + lane.
// Warps >=1: lanes 0-7 left halo (redundant), lanes 8-31 owned.
// Alphas LINEAR at per-warp scale E (actual = la * 2^E).  At each superstep
// start, own+halo values are jointly renormalized IN THE EXPONENT DOMAIN so
// the warp max lands exactly at 2^EBIAS: overflow impossible, 249-bit tail window.
__global__ void __launch_bounds__(NT) ctc_fwd_kernel(
    const float* __restrict__ log_probs,   // [B, T, V]
    const int*   __restrict__ in_len,
    const int*   __restrict__ targets,     // [B, S]
    const int*   __restrict__ tgt_len,
    int T, int V, int S)
{
    __shared__ float sa0[2 * PMAX];
    __shared__ float sa1[2 * PMAX];
    __shared__ float stgl[16 * NT];        // [2][8][NT] thread-private slots
    __shared__ float stgb[16 * NW];        // [2][8][NW] warp-private blank slots
    __shared__ int   sE[2 * NW];           // per-warp scale, double buffered
    __shared__ int   sEf[NW];              // final scales

    const int b    = blockIdx.x;
    const int j    = threadIdx.x;
    const int warp = j >> 5;
    const int lane = j & 31;
    const int p    = 24 * warp + lane;
    const bool owned = (warp == 0) || (lane >= 8);

    int L = tgt_len[b]; if (L > S) L = S;
    int Tin = in_len[b];
    if (Tin > T) Tin = T;
    if (Tin < 1) Tin = 1;

    const float* lp = log_probs + (size_t)b * T * V;
    const int*   tg = targets   + (size_t)b * S;

    const bool act  = (p <= L);
    const bool act1 = (p <  L);
    const bool wact = (24 * warp) <= L;
    int   lab = 0;
    float skf = 0.0f;
    if (act1) {
        lab = tg[p];
        skf = (p >= 1 && lab != tg[p - 1]) ? 1.0f : 0.0f;
    }

    // t = 0: linear alphas at scale E = -EBIAS (max ~= 2^EBIAS)
    float la0 = 0.0f, la1 = 0.0f;
    int   E   = -EBIAS;
    if (p == 0) {
        la0 = ex2f_(lp[0] * LOG2E + (float)EBIAS);
        if (L > 0) la1 = ex2f_(lp[lab] * LOG2E + (float)EBIAS);
    }
    if (owned) { sa0[p] = la0; sa1[p] = la1; }
    if (lane == 0) sE[warp] = E;

    // prologue: stage t=1..8 -> buf0, t=9..16 -> buf1
    if (act) {
        #pragma unroll
        for (int k = 0; k < 8; ++k) { int t = 1 + k; if (t < Tin) cp4(&stgl[k * NT + j], lp + (size_t)t * V + lab); }
    }
    if (wact && lane >= 24) { int k = lane - 24, t = 1 + k; if (t < Tin) cp4(&stgb[k * NW + warp], lp + (size_t)t * V); }
    cp_commit();
    if (act) {
        #pragma unroll
        for (int k = 0; k < 8; ++k) { int t = 9 + k; if (t < Tin) cp4(&stgl[(8 + k) * NT + j], lp + (size_t)t * V + lab); }
    }
    if (wact && lane >= 24) { int k = lane - 24, t = 9 + k; if (t < Tin) cp4(&stgb[(8 + k) * NW + warp], lp + (size_t)t * V); }
    cp_commit();

    int cur = 0;
    for (int tb = 1; tb < Tin; tb += 8, cur ^= 1) {
        cp_wait1();
        __syncthreads();                   // stage[cur] + sa[cur] + sE[cur] visible

        if (wact) {
            // gather candidate values: halo lanes take neighbor data at scale En
            const int En = (warp > 0) ? sE[cur * NW + (warp - 1)] : E;
            float h0 = la0, h1 = la1;
            int   Eh = E;
            if (!owned) {
                h0 = sa0[cur * PMAX + p];
                h1 = sa1[cur * PMAX + p];
                Eh = En;
            }

            // joint renorm in exponent domain: warp max -> exactly 2^EBIAS
            int ie = -0x40000000;
            if (h0 > 0.0f) { int e0 = ((__float_as_int(h0) >> 23) & 255) + Eh; ie = ie > e0 ? ie : e0; }
            if (h1 > 0.0f) { int e1 = ((__float_as_int(h1) >> 23) & 255) + Eh; ie = ie > e1 ? ie : e1; }
            #pragma unroll
            for (int off = 16; off; off >>= 1) {
                int o = __shfl_xor_sync(0xffffffffu, ie, off);
                ie = ie > o ? ie : o;
            }
            if (ie > -0x20000000) {        // some mass in warp
                const int Enew = (ie - 127) - EBIAS;
                la0 = ldx2(h0, Eh - Enew); // shift <= 249 by construction: no overflow
                la1 = ldx2(h1, Eh - Enew);
                E = Enew;
            }

            // staged log-probs -> linear (off-chain MUFU)
            float pl[8], pb[8];
            #pragma unroll
            for (int k = 0; k < 8; ++k) {
                pb[k] = ex2f_(stgb[(cur * 8 + k) * NW + warp] * LOG2E);
                pl[k] = ex2f_(stgl[(cur * 8 + k) * NT + j]   * LOG2E);
            }

            // refill stage[cur] for t = tb+16..tb+23 (self-owned slots)
            if (act) {
                #pragma unroll
                for (int k = 0; k < 8; ++k) { int tn = tb + 16 + k; if (tn < Tin) cp4(&stgl[(cur * 8 + k) * NT + j], lp + (size_t)tn * V + lab); }
            }
            if (lane >= 24) { int k = lane - 24, tn = tb + 16 + k; if (tn < Tin) cp4(&stgb[(cur * 8 + k) * NW + warp], lp + (size_t)tn * V); }

            int rem = Tin - tb; if (rem > 8) rem = 8;
            const int rem0 = act  ? rem : 0;
            const int rem1 = act1 ? rem : 0;

            // ---- 8 steps: pure shfl + FMA, zero MUFU on the chain ----
            #pragma unroll
            for (int k = 0; k < 8; ++k) {
                float o = __shfl_up_sync(0xffffffffu, la1, 1);
                o = (lane == 0) ? 0.0f : o;
                float base = la1 + la0;
                float n1 = fmaf(skf, o, base) * pl[k];
                float n0 = (la0 + o) * pb[k];
                la0 = (k < rem0) ? n0 : la0;
                la1 = (k < rem1) ? n1 : la1;
            }
        }
        cp_commit();                       // uniform; pairs with refills above

        const int nxt = cur ^ 1;
        if (owned) { sa0[nxt * PMAX + p] = la0; sa1[nxt * PMAX + p] = la1; }
        if (lane == 0) sE[nxt * NW + warp] = E;
    }

    // epilogue
    __syncthreads();
    if (owned) { sa0[p] = la0; sa1[p] = la1; }
    if (lane == 0) sEf[warp] = E;
    __syncthreads();
    if (j == 0) {
        // owner warp of pair q: warp 0 owns 0..31; warp w>=1 owns 24w+8..24w+31
        int wx = (L <= 31) ? 0 : (L - 8) / 24;
        float v0 = sa0[L];
        float x = (v0 > 0.0f) ? (lg2f_(v0) + (float)sEf[wx]) : NEGF;
        float y = NEGF;
        if (L > 0) {
            int q = L - 1;
            int wy = (q <= 31) ? 0 : (q - 8) / 24;
            float v1 = sa1[q];
            if (v1 > 0.0f) y = lg2f_(v1) + (float)sEf[wy];
        }
        float ll2 = lae2(x, y);
        float loss = -ll2 * LN2;
        if (!(loss <= 1e29f)) loss = 0.0f;         // zero_infinity (+ nan/inf guard)
        int Lm = (L > 0) ? L : 1;
        g_loss[b] = loss / (float)Lm;
    }
}

__global__ void ctc_reduce_kernel(float* __restrict__ out, int B) {
    int lane = threadIdx.x;
    float s = 0.0f;
    for (int i = lane; i < B; i += 32) s += g_loss[i];
    #pragma unroll
    for (int off = 16; off; off >>= 1)
        s += __shfl_xor_sync(0xffffffffu, s, off);
    if (lane == 0) out[0] = s / (float)B;
}

extern "C" void kernel_launch(void* const* d_in, const int* in_sizes, int n_in,
                              void* d_out, int out_size) {
    const float* log_probs = (const float*)d_in[0];
    const int*   in_len    = (const int*)d_in[1];
    const int*   targets   = (const int*)d_in[2];
    const int*   tgt_len   = (const int*)d_in[3];

    const int B = in_sizes[1];
    const int S = in_sizes[2] / B;
    const int V = 128;
    const int T = in_sizes[0] / (B * V);

    ctc_fwd_kernel<<<B, NT>>>(log_probs, in_len, targets, tgt_len, T, V, S);
    ctc_reduce_kernel<<<1, 32>>>((float*)d_out, B);
}